// round 10
// baseline (speedup 1.0000x reference)
#include <cuda_runtime.h>
#include <cstdint>

// ---------------------------------------------------------------------------
// CRF Viterbi decode, K=16 tags, T up to 1,000,000 steps.
//
// Pipeline:
//   K1 k_chain : sequential bit-exact forward recurrence (16 lanes, tag/lane),
//                BRANCH-FREE hot loop (C++ if{} in the body costs BSSY/BSYNC
//                ~33-56cyc each on sm_103a — this was ~half the runtime).
//   K2 k_bp    : grid-parallel backpointers from fv trace (first-max argmax).
//   K3 k_chunk : per-chunk 16-hypothesis backward chase -> path16 + comp maps.
//   K3b k_seed : sequential composition of chunk maps (tiny), picks seeds.
//   K4 k_out   : parallel select of final path, written as FLOAT32.
//
// Inputs autodetected by element count: 256-element tensor = transitions
// [16,16]; large tensor = sentence [1,T,16].
// ---------------------------------------------------------------------------

#define T_MAX   1000000
#define KT      16
#define CHUNK   2048
#define NCHUNK_MAX ((T_MAX + CHUNK - 1) / CHUNK)   // 489
#define PF      16                                  // feat prefetch depth

__device__ __align__(16) float         g_fv[(size_t)T_MAX * KT];   // 64 MB
__device__ __align__(16) unsigned char g_bp[(size_t)T_MAX * KT];   // 16 MB
__device__ __align__(16) unsigned char g_p16[(size_t)T_MAX * KT];  // 16 MB
__device__ __align__(16) unsigned char g_comp[NCHUNK_MAX * KT];
__device__ __align__(16) unsigned char g_seed[NCHUNK_MAX];

// ---------------------------------------------------------------------------
// K1: sequential value chain. Lane j (0..15) owns tag j.
//   fv_t[j] = max_p( fv_{t-1}[p] + A[j][p] ) + feat_t[j]
// Bit-exact: one FADD per score, exact order-independent max, one feat FADD.
// Hot loop has NO conditionals: stores are unconditional, prefetch loads are
// made unconditional by bounding the main loop at T-PF.
// ---------------------------------------------------------------------------
__global__ void __launch_bounds__(16, 1)
k_chain(const float* __restrict__ feats, const float* __restrict__ trans, int T)
{
    const int j = threadIdx.x;            // 0..15, tag index
    const unsigned MASK = 0xFFFFu;

    // A row j (transitions[next=j][prev=p]) -> registers
    float a[16];
#pragma unroll
    for (int q = 0; q < 4; q++) {
        float4 v = reinterpret_cast<const float4*>(trans)[j * 4 + q];
        a[4 * q + 0] = v.x; a[4 * q + 1] = v.y;
        a[4 * q + 2] = v.z; a[4 * q + 3] = v.w;
    }

    // Feat software pipeline: PF steps ahead (> DRAM latency).
    float fq[PF];
#pragma unroll
    for (int u = 0; u < PF; u++)
        fq[u] = (u < T) ? feats[u * KT + j] : 0.0f;

    float fv = 0.0f;

    // Main loop covers steps [0, nmain) where every prefetch t+PF is valid.
    int nmain = (T > PF) ? (T - PF) : 0;
    nmain -= nmain % PF;                  // multiple of PF

    const float* fptr = feats + (size_t)PF * KT + j;   // prefetch base
    float*       gptr = g_fv + j;                      // store base

    for (int t = 0; t < nmain; t += PF) {
#pragma unroll
        for (int u = 0; u < PF; u++) {
            float s[16];
#pragma unroll
            for (int p = 0; p < 16; p++)
                s[p] = __shfl_sync(MASK, fv, p) + a[p];
            // 4-level exact max tree (order-independent for fp max)
#pragma unroll
            for (int w = 8; w >= 1; w >>= 1)
#pragma unroll
                for (int p = 0; p < w; p++)
                    s[p] = fmaxf(s[p], s[p + w]);
            fv = s[0] + fq[u];
            gptr[u * KT] = fv;                 // unconditional
            fq[u] = fptr[u * KT];              // unconditional prefetch
        }
        gptr += PF * KT;
        fptr += PF * KT;
    }

    // Epilogue: remaining steps (PF..2*PF-1 of them). Branches are fine here.
    int t = nmain;
    for (int u = 0; u < PF && t < T; u++, t++) {
        float s[16];
#pragma unroll
        for (int p = 0; p < 16; p++)
            s[p] = __shfl_sync(MASK, fv, p) + a[p];
#pragma unroll
        for (int w = 8; w >= 1; w >>= 1)
#pragma unroll
            for (int p = 0; p < w; p++)
                s[p] = fmaxf(s[p], s[p + w]);
        fv = s[0] + fq[u];
        g_fv[(size_t)t * KT + j] = fv;
    }
    for (; t < T; t++) {
        float s[16];
#pragma unroll
        for (int p = 0; p < 16; p++)
            s[p] = __shfl_sync(MASK, fv, p) + a[p];
#pragma unroll
        for (int w = 8; w >= 1; w >>= 1)
#pragma unroll
            for (int p = 0; p < w; p++)
                s[p] = fmaxf(s[p], s[p + w]);
        fv = s[0] + feats[(size_t)t * KT + j];
        g_fv[(size_t)t * KT + j] = fv;
    }
}

// ---------------------------------------------------------------------------
// K2: backpointers, grid-parallel. Thread handles (t, i).
// Ascending scan with strict '>' keeps the FIRST max (jnp.argmax semantics).
// Scores recomputed with the identical single FADD -> bit-exact.
// ---------------------------------------------------------------------------
__global__ void k_bp(const float* __restrict__ trans, int T)
{
    int idx = blockIdx.x * blockDim.x + threadIdx.x;
    if (idx >= T * KT) return;
    int t = idx >> 4;
    int i = idx & 15;

    float pv[16];
    if (t == 0) {
#pragma unroll
        for (int p = 0; p < 16; p++) pv[p] = 0.0f;
    } else {
        const float4* row = reinterpret_cast<const float4*>(g_fv + (size_t)(t - 1) * KT);
#pragma unroll
        for (int q = 0; q < 4; q++) {
            float4 v = row[q];
            pv[4 * q + 0] = v.x; pv[4 * q + 1] = v.y;
            pv[4 * q + 2] = v.z; pv[4 * q + 3] = v.w;
        }
    }

    float a[16];
#pragma unroll
    for (int q = 0; q < 4; q++) {
        float4 v = reinterpret_cast<const float4*>(trans)[i * 4 + q];
        a[4 * q + 0] = v.x; a[4 * q + 1] = v.y;
        a[4 * q + 2] = v.z; a[4 * q + 3] = v.w;
    }

    float best = pv[0] + a[0];
    int bi = 0;
#pragma unroll
    for (int p = 1; p < 16; p++) {
        float sc = pv[p] + a[p];
        if (sc > best) { best = sc; bi = p; }
    }
    g_bp[idx] = (unsigned char)bi;
}

// ---------------------------------------------------------------------------
// K3: per-chunk backward chase of all 16 exit-tag hypotheses.
// ---------------------------------------------------------------------------
__global__ void k_chunk(int T)
{
    __shared__ __align__(16) unsigned char sbp[CHUNK * KT];   // 32 KB
    int c = blockIdx.x;
    int s = c * CHUNK;
    int L = min(CHUNK, T - s);

    const int4* src = reinterpret_cast<const int4*>(g_bp + (size_t)s * KT);
    int4* dst = reinterpret_cast<int4*>(sbp);
    for (int i = threadIdx.x; i < L; i += blockDim.x) dst[i] = src[i];
    __syncthreads();

    if (threadIdx.x < 16) {
        int cur = threadIdx.x;                 // hypothesis: z at chunk last idx
        for (int tt = L - 1; tt >= 0; tt--) {
            cur = sbp[tt * KT + cur];
            g_p16[(size_t)(s + tt) * KT + threadIdx.x] = (unsigned char)cur;
        }
        g_comp[c * KT + threadIdx.x] = (unsigned char)cur;
    }
}

// ---------------------------------------------------------------------------
// K3b: compose chunk maps right-to-left. Z starts at argmax(final fv).
// ---------------------------------------------------------------------------
__global__ void k_seed(int T, int C)
{
    __shared__ __align__(16) unsigned char sc[NCHUNK_MAX * KT];
    for (int i = threadIdx.x; i < C * KT; i += blockDim.x) sc[i] = g_comp[i];
    __syncthreads();

    if (threadIdx.x == 0) {
        const float* f = g_fv + (size_t)(T - 1) * KT;
        float best = f[0];
        int Z = 0;
#pragma unroll
        for (int i = 1; i < 16; i++) {
            float v = f[i];
            if (v > best) { best = v; Z = i; }
        }
        for (int c = C - 1; c >= 0; c--) {
            g_seed[c] = (unsigned char)Z;
            Z = sc[c * KT + Z];
        }
    }
}

// ---------------------------------------------------------------------------
// K4: final select.  out[t] = (float) path16[t][ seed[chunk(t)] ]
// ---------------------------------------------------------------------------
__global__ void k_out(float* __restrict__ out, int T)
{
    int t = blockIdx.x * blockDim.x + threadIdx.x;
    if (t < T) {
        int h = g_seed[t / CHUNK];
        out[t] = (float)g_p16[(size_t)t * KT + h];
    }
}

// ---------------------------------------------------------------------------
extern "C" void kernel_launch(void* const* d_in, const int* in_sizes, int n_in,
                              void* d_out, int out_size)
{
    // Input autodetect: transitions is the 256-element tensor,
    // sentence is the large [1,T,16] tensor. Order-independent.
    int fi = 0;
    if (n_in >= 2 && in_sizes[1] > in_sizes[0]) fi = 1;
    const float* feats = (const float*)d_in[fi];
    const float* trans = (const float*)d_in[1 - fi];

    int T = in_sizes[fi] / KT;
    if (T > T_MAX) T = T_MAX;
    if (out_size > 0 && out_size < T) T = out_size;
    if (T < 1) return;
    int C = (T + CHUNK - 1) / CHUNK;

    k_chain<<<1, 16>>>(feats, trans, T);
    k_bp<<<(T * KT + 255) / 256, 256>>>(trans, T);
    k_chunk<<<C, 128>>>(T);
    k_seed<<<1, 128>>>(T, C);
    k_out<<<(T + 255) / 256, 256>>>((float*)d_out, T);
}

// round 11
// speedup vs baseline: 1.1067x; 1.1067x over previous
#include <cuda_runtime.h>
#include <cstdint>

// ---------------------------------------------------------------------------
// CRF Viterbi decode, K=16 tags, T up to 1,000,000 steps.
//
// Pipeline:
//   3x k_dummy : no-op launches to align ncu's -s 5 -c 1 capture window onto
//                k_chain (2 harness launches precede ours; 2+3 skipped = 5).
//   K1 k_chain : sequential bit-exact forward recurrence. 32 lanes; lanes
//                j and j+16 cooperate on tag j (8 predecessors each):
//                8 broadcast SHFLs (minimum possible) + 1 combine SHFL.
//                Hot loop fully unconditional (dual same-value store, bounded
//                main loop makes prefetch in-bounds).
//   K2 k_bp    : grid-parallel backpointers from fv trace (first-max argmax).
//   K3 k_chunk : per-chunk 16-hypothesis backward chase -> path16 + comp maps.
//   K3b k_seed : sequential composition of chunk maps, picks seeds.
//   K4 k_out   : parallel select of final path, written as FLOAT32.
//
// Inputs autodetected by element count: 256-element tensor = transitions
// [16,16]; large tensor = sentence [1,T,16].
// ---------------------------------------------------------------------------

#define T_MAX   1000000
#define KT      16
#define CHUNK   2048
#define NCHUNK_MAX ((T_MAX + CHUNK - 1) / CHUNK)   // 489
#define PF      16                                  // feat prefetch depth

__device__ __align__(16) float         g_fv[(size_t)T_MAX * KT];   // 64 MB
__device__ __align__(16) unsigned char g_bp[(size_t)T_MAX * KT];   // 16 MB
__device__ __align__(16) unsigned char g_p16[(size_t)T_MAX * KT];  // 16 MB
__device__ __align__(16) unsigned char g_comp[NCHUNK_MAX * KT];
__device__ __align__(16) unsigned char g_seed[NCHUNK_MAX];

// ---------------------------------------------------------------------------
// Dummy: shifts ncu capture index so k_chain is the profiled launch.
// ---------------------------------------------------------------------------
__global__ void k_dummy() {}

// ---------------------------------------------------------------------------
// K1: sequential value chain, 1 warp of 32 lanes.
// Lane L: j = L&15 (tag), h = L>>4 (predecessor half).
//   c[p'] = fv[h*8+p'] + A[j][h*8+p']   (one FADD each, bit-exact)
//   3-level exact half-max tree, combine via shfl.xor(16),
//   fv[j] = max + feat[j]               (one FADD, bit-exact).
// fv replicated in both lanes of each pair; both store (same value, benign).
// ---------------------------------------------------------------------------
__global__ void __launch_bounds__(32, 1)
k_chain(const float* __restrict__ feats, const float* __restrict__ trans, int T)
{
    const int L  = threadIdx.x;      // 0..31
    const int j  = L & 15;           // tag
    const int h  = L >> 4;           // half: 0 -> prev 0..7, 1 -> prev 8..15
    const int hb = h * 8;
    const unsigned FULL = 0xFFFFFFFFu;

    // A[j][hb .. hb+7] -> registers (two float4 loads)
    float a0, a1, a2, a3, a4, a5, a6, a7;
    {
        float4 v0 = reinterpret_cast<const float4*>(trans)[j * 4 + h * 2 + 0];
        float4 v1 = reinterpret_cast<const float4*>(trans)[j * 4 + h * 2 + 1];
        a0 = v0.x; a1 = v0.y; a2 = v0.z; a3 = v0.w;
        a4 = v1.x; a5 = v1.y; a6 = v1.z; a7 = v1.w;
    }
    // Loop-invariant shuffle source lanes
    const int s0 = hb + 0, s1 = hb + 1, s2 = hb + 2, s3 = hb + 3;
    const int s4 = hb + 4, s5 = hb + 5, s6 = hb + 6, s7 = hb + 7;

    // Feat software pipeline: PF steps ahead (> DRAM latency).
    float fq[PF];
#pragma unroll
    for (int u = 0; u < PF; u++)
        fq[u] = (u < T) ? feats[u * KT + j] : 0.0f;

    float fv = 0.0f;                 // fv[j], replicated in lanes j and j+16

    // Main loop bound so every prefetch t+u+PF is in-bounds -> no branches.
    int nmain = (T > PF) ? (T - PF) : 0;
    nmain -= nmain % PF;

    const float* fptr = feats + (size_t)PF * KT + j;   // prefetch base
    float*       gptr = g_fv + j;                      // store base

    for (int t = 0; t < nmain; t += PF) {
#pragma unroll
        for (int u = 0; u < PF; u++) {
            float c0 = __shfl_sync(FULL, fv, s0) + a0;
            float c1 = __shfl_sync(FULL, fv, s1) + a1;
            float c2 = __shfl_sync(FULL, fv, s2) + a2;
            float c3 = __shfl_sync(FULL, fv, s3) + a3;
            float c4 = __shfl_sync(FULL, fv, s4) + a4;
            float c5 = __shfl_sync(FULL, fv, s5) + a5;
            float c6 = __shfl_sync(FULL, fv, s6) + a6;
            float c7 = __shfl_sync(FULL, fv, s7) + a7;
            c0 = fmaxf(c0, c4); c1 = fmaxf(c1, c5);
            c2 = fmaxf(c2, c6); c3 = fmaxf(c3, c7);
            c0 = fmaxf(c0, c2); c1 = fmaxf(c1, c3);
            c0 = fmaxf(c0, c1);
            float oth = __shfl_xor_sync(FULL, c0, 16);
            fv = fmaxf(c0, oth) + fq[u];
            gptr[u * KT] = fv;                 // both halves, same value
            fq[u] = fptr[u * KT];              // unconditional prefetch
        }
        gptr += PF * KT;
        fptr += PF * KT;
    }

    // Epilogue: remaining PF..2*PF-1 steps; branches are fine here.
    int t = nmain;
    for (int u = 0; u < PF && t < T; u++, t++) {
        float c0 = __shfl_sync(FULL, fv, s0) + a0;
        float c1 = __shfl_sync(FULL, fv, s1) + a1;
        float c2 = __shfl_sync(FULL, fv, s2) + a2;
        float c3 = __shfl_sync(FULL, fv, s3) + a3;
        float c4 = __shfl_sync(FULL, fv, s4) + a4;
        float c5 = __shfl_sync(FULL, fv, s5) + a5;
        float c6 = __shfl_sync(FULL, fv, s6) + a6;
        float c7 = __shfl_sync(FULL, fv, s7) + a7;
        c0 = fmaxf(c0, c4); c1 = fmaxf(c1, c5);
        c2 = fmaxf(c2, c6); c3 = fmaxf(c3, c7);
        c0 = fmaxf(c0, c2); c1 = fmaxf(c1, c3);
        c0 = fmaxf(c0, c1);
        float oth = __shfl_xor_sync(FULL, c0, 16);
        fv = fmaxf(c0, oth) + fq[u];
        g_fv[(size_t)t * KT + j] = fv;
    }
    for (; t < T; t++) {
        float c0 = __shfl_sync(FULL, fv, s0) + a0;
        float c1 = __shfl_sync(FULL, fv, s1) + a1;
        float c2 = __shfl_sync(FULL, fv, s2) + a2;
        float c3 = __shfl_sync(FULL, fv, s3) + a3;
        float c4 = __shfl_sync(FULL, fv, s4) + a4;
        float c5 = __shfl_sync(FULL, fv, s5) + a5;
        float c6 = __shfl_sync(FULL, fv, s6) + a6;
        float c7 = __shfl_sync(FULL, fv, s7) + a7;
        c0 = fmaxf(c0, c4); c1 = fmaxf(c1, c5);
        c2 = fmaxf(c2, c6); c3 = fmaxf(c3, c7);
        c0 = fmaxf(c0, c2); c1 = fmaxf(c1, c3);
        c0 = fmaxf(c0, c1);
        float oth = __shfl_xor_sync(FULL, c0, 16);
        fv = fmaxf(c0, oth) + feats[(size_t)t * KT + j];
        g_fv[(size_t)t * KT + j] = fv;
    }
}

// ---------------------------------------------------------------------------
// K2: backpointers, grid-parallel. Thread handles (t, i).
// Ascending scan with strict '>' keeps the FIRST max (jnp.argmax semantics).
// Scores recomputed with the identical single FADD -> bit-exact.
// ---------------------------------------------------------------------------
__global__ void k_bp(const float* __restrict__ trans, int T)
{
    int idx = blockIdx.x * blockDim.x + threadIdx.x;
    if (idx >= T * KT) return;
    int t = idx >> 4;
    int i = idx & 15;

    float pv[16];
    if (t == 0) {
#pragma unroll
        for (int p = 0; p < 16; p++) pv[p] = 0.0f;
    } else {
        const float4* row = reinterpret_cast<const float4*>(g_fv + (size_t)(t - 1) * KT);
#pragma unroll
        for (int q = 0; q < 4; q++) {
            float4 v = row[q];
            pv[4 * q + 0] = v.x; pv[4 * q + 1] = v.y;
            pv[4 * q + 2] = v.z; pv[4 * q + 3] = v.w;
        }
    }

    float a[16];
#pragma unroll
    for (int q = 0; q < 4; q++) {
        float4 v = reinterpret_cast<const float4*>(trans)[i * 4 + q];
        a[4 * q + 0] = v.x; a[4 * q + 1] = v.y;
        a[4 * q + 2] = v.z; a[4 * q + 3] = v.w;
    }

    float best = pv[0] + a[0];
    int bi = 0;
#pragma unroll
    for (int p = 1; p < 16; p++) {
        float sc = pv[p] + a[p];
        if (sc > best) { best = sc; bi = p; }
    }
    g_bp[idx] = (unsigned char)bi;
}

// ---------------------------------------------------------------------------
// K3: per-chunk backward chase of all 16 exit-tag hypotheses.
// ---------------------------------------------------------------------------
__global__ void k_chunk(int T)
{
    __shared__ __align__(16) unsigned char sbp[CHUNK * KT];   // 32 KB
    int c = blockIdx.x;
    int s = c * CHUNK;
    int L = min(CHUNK, T - s);

    const int4* src = reinterpret_cast<const int4*>(g_bp + (size_t)s * KT);
    int4* dst = reinterpret_cast<int4*>(sbp);
    for (int i = threadIdx.x; i < L; i += blockDim.x) dst[i] = src[i];
    __syncthreads();

    if (threadIdx.x < 16) {
        int cur = threadIdx.x;                 // hypothesis: z at chunk last idx
        for (int tt = L - 1; tt >= 0; tt--) {
            cur = sbp[tt * KT + cur];
            g_p16[(size_t)(s + tt) * KT + threadIdx.x] = (unsigned char)cur;
        }
        g_comp[c * KT + threadIdx.x] = (unsigned char)cur;
    }
}

// ---------------------------------------------------------------------------
// K3b: compose chunk maps right-to-left. Z starts at argmax(final fv).
// ---------------------------------------------------------------------------
__global__ void k_seed(int T, int C)
{
    __shared__ __align__(16) unsigned char sc[NCHUNK_MAX * KT];
    for (int i = threadIdx.x; i < C * KT; i += blockDim.x) sc[i] = g_comp[i];
    __syncthreads();

    if (threadIdx.x == 0) {
        const float* f = g_fv + (size_t)(T - 1) * KT;
        float best = f[0];
        int Z = 0;
#pragma unroll
        for (int i = 1; i < 16; i++) {
            float v = f[i];
            if (v > best) { best = v; Z = i; }
        }
        for (int c = C - 1; c >= 0; c--) {
            g_seed[c] = (unsigned char)Z;
            Z = sc[c * KT + Z];
        }
    }
}

// ---------------------------------------------------------------------------
// K4: final select.  out[t] = (float) path16[t][ seed[chunk(t)] ]
// ---------------------------------------------------------------------------
__global__ void k_out(float* __restrict__ out, int T)
{
    int t = blockIdx.x * blockDim.x + threadIdx.x;
    if (t < T) {
        int h = g_seed[t / CHUNK];
        out[t] = (float)g_p16[(size_t)t * KT + h];
    }
}

// ---------------------------------------------------------------------------
extern "C" void kernel_launch(void* const* d_in, const int* in_sizes, int n_in,
                              void* d_out, int out_size)
{
    // Input autodetect: transitions is the 256-element tensor,
    // sentence is the large [1,T,16] tensor. Order-independent.
    int fi = 0;
    if (n_in >= 2 && in_sizes[1] > in_sizes[0]) fi = 1;
    const float* feats = (const float*)d_in[fi];
    const float* trans = (const float*)d_in[1 - fi];

    int T = in_sizes[fi] / KT;
    if (T > T_MAX) T = T_MAX;
    if (out_size > 0 && out_size < T) T = out_size;
    if (T < 1) return;
    int C = (T + CHUNK - 1) / CHUNK;

    // Align ncu capture (-s 5 -c 1) onto k_chain: 2 harness launches + these
    // 3 dummies fill the 5-launch skip window.
    k_dummy<<<1, 32>>>();
    k_dummy<<<1, 32>>>();
    k_dummy<<<1, 32>>>();

    k_chain<<<1, 32>>>(feats, trans, T);
    k_bp<<<(T * KT + 255) / 256, 256>>>(trans, T);
    k_chunk<<<C, 128>>>(T);
    k_seed<<<1, 128>>>(T, C);
    k_out<<<(T + 255) / 256, 256>>>((float*)d_out, T);
}

// round 12
// speedup vs baseline: 1.3914x; 1.2573x over previous
#include <cuda_runtime.h>
#include <cstdint>

// ---------------------------------------------------------------------------
// CRF Viterbi decode, K=16 tags, T up to 1,000,000 steps.
//
//   2x k_dummy : align ncu -s 5 -c 1 capture onto k_chain.
//   K0 k_tr    : transpose feats [T][16] -> g_ftr[16][T] (bandwidth-parallel).
//   K1 k_chain : sequential bit-exact forward recurrence, 16 lanes.
//                Broadcast via SHARED MEMORY (STS + BAR + 4x LDS.128) instead
//                of shuffles: single-warp SHFLs cost ~8cyc issue each (measured
//                across R8-R11); smem broadcast avoids the MIO shuffle tax.
//                Double-buffered slots; BAR (floor 3-7 @1 warp) provides the
//                STS->LDS fence (BAR drains pending STS natively).
//                Feat reads & fv writes vectorized via transposed layouts:
//                1 LDG.128 + 1 STG.128 per 4 steps.
//   K2 k_bp    : grid-parallel backpointers (first-max argmax, bit-exact).
//   K3 k_chunk : per-chunk 16-hypothesis backward chase.
//   K3b k_seed : sequential composition of chunk maps.
//   K4 k_out   : parallel select, FLOAT32 output.
// ---------------------------------------------------------------------------

#define T_MAX   1000000
#define KT      16
#define CHUNK   2048
#define NCHUNK_MAX ((T_MAX + CHUNK - 1) / CHUNK)   // 489

__device__ __align__(16) float         g_ftr[(size_t)KT * T_MAX];  // feats^T [j][t]
__device__ __align__(16) float         g_fvt[(size_t)KT * T_MAX];  // fv^T    [j][t]
__device__ __align__(16) unsigned char g_bp[(size_t)T_MAX * KT];
__device__ __align__(16) unsigned char g_p16[(size_t)T_MAX * KT];
__device__ __align__(16) unsigned char g_comp[NCHUNK_MAX * KT];
__device__ __align__(16) unsigned char g_seed[NCHUNK_MAX];

__global__ void k_dummy() {}

// ---------------------------------------------------------------------------
// K0: transpose feats [T][16] -> g_ftr[16][T_MAX]. 64-t x 16-j tiles.
// ---------------------------------------------------------------------------
__global__ void k_tr(const float* __restrict__ feats, int T)
{
    __shared__ float tile[16][65];
    int t0  = blockIdx.x * 64;
    int lin = threadIdx.x;            // 256 threads
    int jj  = lin & 15;
    int tb  = lin >> 4;               // 0..15
#pragma unroll
    for (int r = 0; r < 4; r++) {
        int tl = tb + r * 16;
        int t  = t0 + tl;
        tile[jj][tl] = (t < T) ? feats[(size_t)t * KT + jj] : 0.0f;
    }
    __syncthreads();
#pragma unroll
    for (int r = 0; r < 4; r++) {
        int idx = lin + r * 256;
        int j2  = idx >> 6;           // 0..15
        int tl  = idx & 63;
        int t   = t0 + tl;
        if (t < T) g_ftr[(size_t)j2 * T_MAX + t] = tile[j2][tl];
    }
}

// ---------------------------------------------------------------------------
// K1: one step of the chain. Broadcast fv via smem slot S, then
//   fv' = max_p( fv[p] + a[p] ) + feat     (bit-exact vs reference)
// ---------------------------------------------------------------------------
__device__ __forceinline__ float chain_step(volatile float* S, int j, float fv,
                                            float feat, const float* a)
{
    S[j] = fv;
    __syncthreads();                  // 1-warp BAR: drains STS, fences RAW
    float4 v0 = *(const float4*)(S + 0);
    float4 v1 = *(const float4*)(S + 4);
    float4 v2 = *(const float4*)(S + 8);
    float4 v3 = *(const float4*)(S + 12);
    float s0  = v0.x + a[0],  s1  = v0.y + a[1];
    float s2  = v0.z + a[2],  s3  = v0.w + a[3];
    float s4  = v1.x + a[4],  s5  = v1.y + a[5];
    float s6  = v1.z + a[6],  s7  = v1.w + a[7];
    float s8  = v2.x + a[8],  s9  = v2.y + a[9];
    float s10 = v2.z + a[10], s11 = v2.w + a[11];
    float s12 = v3.x + a[12], s13 = v3.y + a[13];
    float s14 = v3.z + a[14], s15 = v3.w + a[15];
    // exact max tree (fp max is order-independent)
    s0 = fmaxf(s0, s8);   s1 = fmaxf(s1, s9);
    s2 = fmaxf(s2, s10);  s3 = fmaxf(s3, s11);
    s4 = fmaxf(s4, s12);  s5 = fmaxf(s5, s13);
    s6 = fmaxf(s6, s14);  s7 = fmaxf(s7, s15);
    s0 = fmaxf(s0, s4);   s1 = fmaxf(s1, s5);
    s2 = fmaxf(s2, s6);   s3 = fmaxf(s3, s7);
    s0 = fmaxf(s0, s2);   s1 = fmaxf(s1, s3);
    s0 = fmaxf(s0, s1);
    return s0 + feat;
}

__global__ void __launch_bounds__(16, 1)
k_chain(const float* __restrict__ trans, int T)
{
    __shared__ __align__(64) float sA[16];
    __shared__ __align__(64) float sB[16];
    const int j = threadIdx.x;        // tag

    float a[16];
#pragma unroll
    for (int q = 0; q < 4; q++) {
        float4 v = reinterpret_cast<const float4*>(trans)[j * 4 + q];
        a[4 * q + 0] = v.x; a[4 * q + 1] = v.y;
        a[4 * q + 2] = v.z; a[4 * q + 3] = v.w;
    }

    const float* fj = g_ftr + (size_t)j * T_MAX;   // my feat row (transposed)
    float*       oj = g_fvt + (size_t)j * T_MAX;   // my fv row (transposed)

    float fv = 0.0f;

    // Main loop: groups of 16 steps; group g prefetches group g+1.
    // G chosen so prefetch (steps (g+1)*16 .. +15) is always in-bounds.
    int G = (T >= 32) ? ((T - 16) / 16) : 0;

    float4 cur[4], nxt[4];
    if (G > 0) {
#pragma unroll
        for (int q = 0; q < 4; q++) cur[q] = *(const float4*)(fj + q * 4);
    }

    for (int g = 0; g < G; g++) {
        const float* pf = fj + (size_t)(g + 1) * 16;
#pragma unroll
        for (int q = 0; q < 4; q++) nxt[q] = *(const float4*)(pf + q * 4);
        float* po = oj + (size_t)g * 16;
#pragma unroll
        for (int q = 0; q < 4; q++) {
            float4 f4 = cur[q];
            float4 acc;
            acc.x = fv = chain_step(sA, j, fv, f4.x, a);
            acc.y = fv = chain_step(sB, j, fv, f4.y, a);
            acc.z = fv = chain_step(sA, j, fv, f4.z, a);
            acc.w = fv = chain_step(sB, j, fv, f4.w, a);
            *(float4*)(po + q * 4) = acc;
        }
#pragma unroll
        for (int q = 0; q < 4; q++) cur[q] = nxt[q];
    }

    // Epilogue: remaining steps, scalar, parity continues (t&1).
    for (int t = G * 16; t < T; t++) {
        float* S = (t & 1) ? sB : sA;
        fv = chain_step(S, j, fv, fj[t], a);
        oj[t] = fv;
    }
}

// ---------------------------------------------------------------------------
// K2: backpointers, grid-parallel. Thread handles (t, i).
// Strict '>' ascending scan keeps FIRST max (jnp.argmax). Scores recomputed
// with the identical single FADD -> bit-exact. Reads transposed fv.
// ---------------------------------------------------------------------------
__global__ void k_bp(const float* __restrict__ trans, int T)
{
    int idx = blockIdx.x * blockDim.x + threadIdx.x;
    if (idx >= T * KT) return;
    int t = idx >> 4;
    int i = idx & 15;

    float pv[16];
    if (t == 0) {
#pragma unroll
        for (int p = 0; p < 16; p++) pv[p] = 0.0f;
    } else {
#pragma unroll
        for (int p = 0; p < 16; p++)
            pv[p] = g_fvt[(size_t)p * T_MAX + (t - 1)];
    }

    float a[16];
#pragma unroll
    for (int q = 0; q < 4; q++) {
        float4 v = reinterpret_cast<const float4*>(trans)[i * 4 + q];
        a[4 * q + 0] = v.x; a[4 * q + 1] = v.y;
        a[4 * q + 2] = v.z; a[4 * q + 3] = v.w;
    }

    float best = pv[0] + a[0];
    int bi = 0;
#pragma unroll
    for (int p = 1; p < 16; p++) {
        float sc = pv[p] + a[p];
        if (sc > best) { best = sc; bi = p; }
    }
    g_bp[idx] = (unsigned char)bi;
}

// ---------------------------------------------------------------------------
// K3: per-chunk backward chase of all 16 exit-tag hypotheses.
// ---------------------------------------------------------------------------
__global__ void k_chunk(int T)
{
    __shared__ __align__(16) unsigned char sbp[CHUNK * KT];   // 32 KB
    int c = blockIdx.x;
    int s = c * CHUNK;
    int L = min(CHUNK, T - s);

    const int4* src = reinterpret_cast<const int4*>(g_bp + (size_t)s * KT);
    int4* dst = reinterpret_cast<int4*>(sbp);
    for (int i = threadIdx.x; i < L; i += blockDim.x) dst[i] = src[i];
    __syncthreads();

    if (threadIdx.x < 16) {
        int cur = threadIdx.x;
        for (int tt = L - 1; tt >= 0; tt--) {
            cur = sbp[tt * KT + cur];
            g_p16[(size_t)(s + tt) * KT + threadIdx.x] = (unsigned char)cur;
        }
        g_comp[c * KT + threadIdx.x] = (unsigned char)cur;
    }
}

// ---------------------------------------------------------------------------
// K3b: compose chunk maps right-to-left. Z starts at argmax(final fv).
// ---------------------------------------------------------------------------
__global__ void k_seed(int T, int C)
{
    __shared__ __align__(16) unsigned char sc[NCHUNK_MAX * KT];
    for (int i = threadIdx.x; i < C * KT; i += blockDim.x) sc[i] = g_comp[i];
    __syncthreads();

    if (threadIdx.x == 0) {
        float best = g_fvt[(size_t)0 * T_MAX + (T - 1)];
        int Z = 0;
#pragma unroll
        for (int i = 1; i < 16; i++) {
            float v = g_fvt[(size_t)i * T_MAX + (T - 1)];
            if (v > best) { best = v; Z = i; }
        }
        for (int c = C - 1; c >= 0; c--) {
            g_seed[c] = (unsigned char)Z;
            Z = sc[c * KT + Z];
        }
    }
}

// ---------------------------------------------------------------------------
// K4: final select.  out[t] = (float) path16[t][ seed[chunk(t)] ]
// ---------------------------------------------------------------------------
__global__ void k_out(float* __restrict__ out, int T)
{
    int t = blockIdx.x * blockDim.x + threadIdx.x;
    if (t < T) {
        int h = g_seed[t / CHUNK];
        out[t] = (float)g_p16[(size_t)t * KT + h];
    }
}

// ---------------------------------------------------------------------------
extern "C" void kernel_launch(void* const* d_in, const int* in_sizes, int n_in,
                              void* d_out, int out_size)
{
    // Input autodetect: transitions = 256-element tensor; sentence = large.
    int fi = 0;
    if (n_in >= 2 && in_sizes[1] > in_sizes[0]) fi = 1;
    const float* feats = (const float*)d_in[fi];
    const float* trans = (const float*)d_in[1 - fi];

    int T = in_sizes[fi] / KT;
    if (T > T_MAX) T = T_MAX;
    if (out_size > 0 && out_size < T) T = out_size;
    if (T < 1) return;
    int C = (T + CHUNK - 1) / CHUNK;

    // ncu alignment: 2 harness launches + 2 dummies + k_tr = 5 skipped,
    // capture lands on k_chain.
    k_dummy<<<1, 32>>>();
    k_dummy<<<1, 32>>>();

    k_tr<<<(T + 63) / 64, 256>>>(feats, T);
    k_chain<<<1, 16>>>(trans, T);
    k_bp<<<(T * KT + 255) / 256, 256>>>(trans, T);
    k_chunk<<<C, 128>>>(T);
    k_seed<<<1, 128>>>(T, C);
    k_out<<<(T + 255) / 256, 256>>>((float*)d_out, T);
}

// round 13
// speedup vs baseline: 1.4822x; 1.0653x over previous
#include <cuda_runtime.h>
#include <cstdint>

// ---------------------------------------------------------------------------
// CRF Viterbi decode, K=16 tags, T up to 1,000,000 steps.
//
//   2x k_dummy : align ncu -s 5 -c 1 capture onto k_chain.
//   K0 k_tr    : transpose feats [T][16] -> g_ftr[16][T] (bandwidth-parallel).
//   K1 k_chain : sequential bit-exact forward recurrence, 16 lanes.
//                smem broadcast (STS + BAR + 4x LDS.128) + PACKED f32x2 adds:
//                add.rn.f32x2 halves the fma-pipe issue cost of the 16
//                broadcast adds (2 IEEE-rn adds/instr, bit-exact). Packing is
//                free: smem read as ulonglong2, unpack = register aliasing.
//                Scalar FMNMX tree rides the alu pipe (dual-issues vs fma).
//   K2 k_bp    : grid-parallel backpointers (first-max argmax, bit-exact).
//   K3 k_chunk : per-chunk 16-hypothesis backward chase.
//   K3b k_seed : sequential composition of chunk maps.
//   K4 k_out   : parallel select, FLOAT32 output.
// ---------------------------------------------------------------------------

#define T_MAX   1000000
#define KT      16
#define CHUNK   2048
#define NCHUNK_MAX ((T_MAX + CHUNK - 1) / CHUNK)   // 489

__device__ __align__(16) float         g_ftr[(size_t)KT * T_MAX];  // feats^T [j][t]
__device__ __align__(16) float         g_fvt[(size_t)KT * T_MAX];  // fv^T    [j][t]
__device__ __align__(16) unsigned char g_bp[(size_t)T_MAX * KT];
__device__ __align__(16) unsigned char g_p16[(size_t)T_MAX * KT];
__device__ __align__(16) unsigned char g_comp[NCHUNK_MAX * KT];
__device__ __align__(16) unsigned char g_seed[NCHUNK_MAX];

// Packed fp32 helpers (sm_100+ PTX). add.rn.f32x2 = two independent IEEE-rn
// fp32 adds -> bit-exact vs scalar FADD.
#define ADDX2(out, x, y) \
    asm("add.rn.f32x2 %0, %1, %2;" : "=l"(out) : "l"(x), "l"(y))
#define PKX2(out, lo, hi) \
    asm("mov.b64 %0, {%1, %2};" : "=l"(out) : "f"(lo), "f"(hi))
#define UNPKX2(lo, hi, in) \
    asm("mov.b64 {%0, %1}, %2;" : "=f"(lo), "=f"(hi) : "l"(in))

__global__ void k_dummy() {}

// ---------------------------------------------------------------------------
// K0: transpose feats [T][16] -> g_ftr[16][T_MAX]. 64-t x 16-j tiles.
// ---------------------------------------------------------------------------
__global__ void k_tr(const float* __restrict__ feats, int T)
{
    __shared__ float tile[16][65];
    int t0  = blockIdx.x * 64;
    int lin = threadIdx.x;            // 256 threads
    int jj  = lin & 15;
    int tb  = lin >> 4;               // 0..15
#pragma unroll
    for (int r = 0; r < 4; r++) {
        int tl = tb + r * 16;
        int t  = t0 + tl;
        tile[jj][tl] = (t < T) ? feats[(size_t)t * KT + jj] : 0.0f;
    }
    __syncthreads();
#pragma unroll
    for (int r = 0; r < 4; r++) {
        int idx = lin + r * 256;
        int j2  = idx >> 6;           // 0..15
        int tl  = idx & 63;
        int t   = t0 + tl;
        if (t < T) g_ftr[(size_t)j2 * T_MAX + t] = tile[j2][tl];
    }
}

// ---------------------------------------------------------------------------
// One chain step: broadcast fv via smem slot S, then
//   fv' = max_p( fv[p] + a[p] ) + feat     (bit-exact vs reference)
// 16 adds done as 8 packed f32x2 adds; exact scalar max tree.
// ---------------------------------------------------------------------------
__device__ __forceinline__ float chain_step(
    float* S, int j, float fv, float feat,
    unsigned long long k0, unsigned long long k1,
    unsigned long long k2, unsigned long long k3,
    unsigned long long k4, unsigned long long k5,
    unsigned long long k6, unsigned long long k7)
{
    S[j] = fv;
    __syncthreads();                  // 1-warp BAR (floor 3-7): STS->LDS fence
    ulonglong2 w0 = *(const ulonglong2*)(S + 0);
    ulonglong2 w1 = *(const ulonglong2*)(S + 4);
    ulonglong2 w2 = *(const ulonglong2*)(S + 8);
    ulonglong2 w3 = *(const ulonglong2*)(S + 12);
    unsigned long long c0, c1, c2, c3, c4, c5, c6, c7;
    ADDX2(c0, w0.x, k0);  ADDX2(c1, w0.y, k1);
    ADDX2(c2, w1.x, k2);  ADDX2(c3, w1.y, k3);
    ADDX2(c4, w2.x, k4);  ADDX2(c5, w2.y, k5);
    ADDX2(c6, w3.x, k6);  ADDX2(c7, w3.y, k7);
    float v0, v1, v2, v3, v4, v5, v6, v7;
    float v8, v9, v10, v11, v12, v13, v14, v15;
    UNPKX2(v0,  v1,  c0);  UNPKX2(v2,  v3,  c1);
    UNPKX2(v4,  v5,  c2);  UNPKX2(v6,  v7,  c3);
    UNPKX2(v8,  v9,  c4);  UNPKX2(v10, v11, c5);
    UNPKX2(v12, v13, c6);  UNPKX2(v14, v15, c7);
    // exact max tree (fp max is order-independent)
    v0 = fmaxf(v0, v8);   v1 = fmaxf(v1, v9);
    v2 = fmaxf(v2, v10);  v3 = fmaxf(v3, v11);
    v4 = fmaxf(v4, v12);  v5 = fmaxf(v5, v13);
    v6 = fmaxf(v6, v14);  v7 = fmaxf(v7, v15);
    v0 = fmaxf(v0, v4);   v1 = fmaxf(v1, v5);
    v2 = fmaxf(v2, v6);   v3 = fmaxf(v3, v7);
    v0 = fmaxf(v0, v2);   v1 = fmaxf(v1, v3);
    v0 = fmaxf(v0, v1);
    return v0 + feat;
}

__global__ void __launch_bounds__(16, 1)
k_chain(const float* __restrict__ trans, int T)
{
    __shared__ __align__(64) float sA[16];
    __shared__ __align__(64) float sB[16];
    const int j = threadIdx.x;        // tag

    // A row j packed into 8 f32x2 constants (pairs of adjacent predecessors)
    unsigned long long k0, k1, k2, k3, k4, k5, k6, k7;
    {
        float4 q0 = reinterpret_cast<const float4*>(trans)[j * 4 + 0];
        float4 q1 = reinterpret_cast<const float4*>(trans)[j * 4 + 1];
        float4 q2 = reinterpret_cast<const float4*>(trans)[j * 4 + 2];
        float4 q3 = reinterpret_cast<const float4*>(trans)[j * 4 + 3];
        PKX2(k0, q0.x, q0.y);  PKX2(k1, q0.z, q0.w);
        PKX2(k2, q1.x, q1.y);  PKX2(k3, q1.z, q1.w);
        PKX2(k4, q2.x, q2.y);  PKX2(k5, q2.z, q2.w);
        PKX2(k6, q3.x, q3.y);  PKX2(k7, q3.z, q3.w);
    }

    const float* fj = g_ftr + (size_t)j * T_MAX;   // my feat row (transposed)
    float*       oj = g_fvt + (size_t)j * T_MAX;   // my fv row (transposed)

    float fv = 0.0f;

    // Main loop: groups of 16 steps; group g prefetches group g+1.
    int G = (T >= 32) ? ((T - 16) / 16) : 0;

    float4 cur[4], nxt[4];
    if (G > 0) {
#pragma unroll
        for (int q = 0; q < 4; q++) cur[q] = *(const float4*)(fj + q * 4);
    }

    for (int g = 0; g < G; g++) {
        const float* pf = fj + (size_t)(g + 1) * 16;
#pragma unroll
        for (int q = 0; q < 4; q++) nxt[q] = *(const float4*)(pf + q * 4);
        float* po = oj + (size_t)g * 16;
#pragma unroll
        for (int q = 0; q < 4; q++) {
            float4 f4 = cur[q];
            float4 acc;
            acc.x = fv = chain_step(sA, j, fv, f4.x, k0,k1,k2,k3,k4,k5,k6,k7);
            acc.y = fv = chain_step(sB, j, fv, f4.y, k0,k1,k2,k3,k4,k5,k6,k7);
            acc.z = fv = chain_step(sA, j, fv, f4.z, k0,k1,k2,k3,k4,k5,k6,k7);
            acc.w = fv = chain_step(sB, j, fv, f4.w, k0,k1,k2,k3,k4,k5,k6,k7);
            *(float4*)(po + q * 4) = acc;
        }
#pragma unroll
        for (int q = 0; q < 4; q++) cur[q] = nxt[q];
    }

    // Epilogue: remaining steps, scalar, parity continues.
    for (int t = G * 16; t < T; t++) {
        float* S = (t & 1) ? sB : sA;
        fv = chain_step(S, j, fv, fj[t], k0,k1,k2,k3,k4,k5,k6,k7);
        oj[t] = fv;
    }
}

// ---------------------------------------------------------------------------
// K2: backpointers, grid-parallel. Thread handles (t, i).
// Strict '>' ascending scan keeps FIRST max (jnp.argmax). Scores recomputed
// with the identical single FADD -> bit-exact. Reads transposed fv.
// ---------------------------------------------------------------------------
__global__ void k_bp(const float* __restrict__ trans, int T)
{
    int idx = blockIdx.x * blockDim.x + threadIdx.x;
    if (idx >= T * KT) return;
    int t = idx >> 4;
    int i = idx & 15;

    float pv[16];
    if (t == 0) {
#pragma unroll
        for (int p = 0; p < 16; p++) pv[p] = 0.0f;
    } else {
#pragma unroll
        for (int p = 0; p < 16; p++)
            pv[p] = g_fvt[(size_t)p * T_MAX + (t - 1)];
    }

    float a[16];
#pragma unroll
    for (int q = 0; q < 4; q++) {
        float4 v = reinterpret_cast<const float4*>(trans)[i * 4 + q];
        a[4 * q + 0] = v.x; a[4 * q + 1] = v.y;
        a[4 * q + 2] = v.z; a[4 * q + 3] = v.w;
    }

    float best = pv[0] + a[0];
    int bi = 0;
#pragma unroll
    for (int p = 1; p < 16; p++) {
        float sc = pv[p] + a[p];
        if (sc > best) { best = sc; bi = p; }
    }
    g_bp[idx] = (unsigned char)bi;
}

// ---------------------------------------------------------------------------
// K3: per-chunk backward chase of all 16 exit-tag hypotheses.
// ---------------------------------------------------------------------------
__global__ void k_chunk(int T)
{
    __shared__ __align__(16) unsigned char sbp[CHUNK * KT];   // 32 KB
    int c = blockIdx.x;
    int s = c * CHUNK;
    int L = min(CHUNK, T - s);

    const int4* src = reinterpret_cast<const int4*>(g_bp + (size_t)s * KT);
    int4* dst = reinterpret_cast<int4*>(sbp);
    for (int i = threadIdx.x; i < L; i += blockDim.x) dst[i] = src[i];
    __syncthreads();

    if (threadIdx.x < 16) {
        int cur = threadIdx.x;
        for (int tt = L - 1; tt >= 0; tt--) {
            cur = sbp[tt * KT + cur];
            g_p16[(size_t)(s + tt) * KT + threadIdx.x] = (unsigned char)cur;
        }
        g_comp[c * KT + threadIdx.x] = (unsigned char)cur;
    }
}

// ---------------------------------------------------------------------------
// K3b: compose chunk maps right-to-left. Z starts at argmax(final fv).
// ---------------------------------------------------------------------------
__global__ void k_seed(int T, int C)
{
    __shared__ __align__(16) unsigned char sc[NCHUNK_MAX * KT];
    for (int i = threadIdx.x; i < C * KT; i += blockDim.x) sc[i] = g_comp[i];
    __syncthreads();

    if (threadIdx.x == 0) {
        float best = g_fvt[(size_t)0 * T_MAX + (T - 1)];
        int Z = 0;
#pragma unroll
        for (int i = 1; i < 16; i++) {
            float v = g_fvt[(size_t)i * T_MAX + (T - 1)];
            if (v > best) { best = v; Z = i; }
        }
        for (int c = C - 1; c >= 0; c--) {
            g_seed[c] = (unsigned char)Z;
            Z = sc[c * KT + Z];
        }
    }
}

// ---------------------------------------------------------------------------
// K4: final select.  out[t] = (float) path16[t][ seed[chunk(t)] ]
// ---------------------------------------------------------------------------
__global__ void k_out(float* __restrict__ out, int T)
{
    int t = blockIdx.x * blockDim.x + threadIdx.x;
    if (t < T) {
        int h = g_seed[t / CHUNK];
        out[t] = (float)g_p16[(size_t)t * KT + h];
    }
}

// ---------------------------------------------------------------------------
extern "C" void kernel_launch(void* const* d_in, const int* in_sizes, int n_in,
                              void* d_out, int out_size)
{
    // Input autodetect: transitions = 256-element tensor; sentence = large.
    int fi = 0;
    if (n_in >= 2 && in_sizes[1] > in_sizes[0]) fi = 1;
    const float* feats = (const float*)d_in[fi];
    const float* trans = (const float*)d_in[1 - fi];

    int T = in_sizes[fi] / KT;
    if (T > T_MAX) T = T_MAX;
    if (out_size > 0 && out_size < T) T = out_size;
    if (T < 1) return;
    int C = (T + CHUNK - 1) / CHUNK;

    // ncu alignment: 2 harness launches + 2 dummies + k_tr = 5 skipped,
    // capture lands on k_chain.
    k_dummy<<<1, 32>>>();
    k_dummy<<<1, 32>>>();

    k_tr<<<(T + 63) / 64, 256>>>(feats, T);
    k_chain<<<1, 16>>>(trans, T);
    k_bp<<<(T * KT + 255) / 256, 256>>>(trans, T);
    k_chunk<<<C, 128>>>(T);
    k_seed<<<1, 128>>>(T, C);
    k_out<<<(T + 255) / 256, 256>>>((float*)d_out, T);
}

// round 14
// speedup vs baseline: 1.6791x; 1.1328x over previous
#include <cuda_runtime.h>
#include <cstdint>

// ---------------------------------------------------------------------------
// CRF Viterbi decode, K=16 tags, T up to 1,000,000 steps.
//
//   2x k_dummy : align ncu -s 5 -c 1 capture onto k_chain.
//   K0 k_tr    : transpose feats [T][16] -> g_ftr[16][T] (bandwidth-parallel).
//   K1 k_chain : sequential bit-exact forward recurrence, 16 lanes = 1 warp.
//                WARP-SYNCHRONOUS smem broadcast: no __syncthreads. A single
//                converged warp's smem ops are processed in issue order by the
//                in-order LSU, so ld.shared after st.shared sees the data.
//                asm volatile + "memory" pins compiler ordering. Removes the
//                BAR (+STS drain + deferred block) that R13 profiling showed
//                to be ~40-60 cyc of the ~120 cyc/step chain.
//                Loads as ld.shared.v2.b64 -> feed add.rn.f32x2 directly.
//   K2 k_bp    : grid-parallel backpointers (first-max argmax, bit-exact).
//   K3 k_chunk : per-chunk 16-hypothesis backward chase.
//   K3b k_seed : sequential composition of chunk maps.
//   K4 k_out   : parallel select, FLOAT32 output.
// ---------------------------------------------------------------------------

#define T_MAX   1000000
#define KT      16
#define CHUNK   2048
#define NCHUNK_MAX ((T_MAX + CHUNK - 1) / CHUNK)   // 489

__device__ __align__(16) float         g_ftr[(size_t)KT * T_MAX];  // feats^T [j][t]
__device__ __align__(16) float         g_fvt[(size_t)KT * T_MAX];  // fv^T    [j][t]
__device__ __align__(16) unsigned char g_bp[(size_t)T_MAX * KT];
__device__ __align__(16) unsigned char g_p16[(size_t)T_MAX * KT];
__device__ __align__(16) unsigned char g_comp[NCHUNK_MAX * KT];
__device__ __align__(16) unsigned char g_seed[NCHUNK_MAX];

// Packed fp32 helpers. add.rn.f32x2 = two independent IEEE-rn fp32 adds ->
// bit-exact vs scalar FADD.
#define ADDX2(out, x, y) \
    asm("add.rn.f32x2 %0, %1, %2;" : "=l"(out) : "l"(x), "l"(y))
#define PKX2(out, lo, hi) \
    asm("mov.b64 %0, {%1, %2};" : "=l"(out) : "f"(lo), "f"(hi))
#define UNPKX2(lo, hi, in) \
    asm("mov.b64 {%0, %1}, %2;" : "=f"(lo), "=f"(hi) : "l"(in))

__global__ void k_dummy() {}

// ---------------------------------------------------------------------------
// K0: transpose feats [T][16] -> g_ftr[16][T_MAX]. 64-t x 16-j tiles.
// ---------------------------------------------------------------------------
__global__ void k_tr(const float* __restrict__ feats, int T)
{
    __shared__ float tile[16][65];
    int t0  = blockIdx.x * 64;
    int lin = threadIdx.x;            // 256 threads
    int jj  = lin & 15;
    int tb  = lin >> 4;               // 0..15
#pragma unroll
    for (int r = 0; r < 4; r++) {
        int tl = tb + r * 16;
        int t  = t0 + tl;
        tile[jj][tl] = (t < T) ? feats[(size_t)t * KT + jj] : 0.0f;
    }
    __syncthreads();
#pragma unroll
    for (int r = 0; r < 4; r++) {
        int idx = lin + r * 256;
        int j2  = idx >> 6;           // 0..15
        int tl  = idx & 63;
        int t   = t0 + tl;
        if (t < T) g_ftr[(size_t)j2 * T_MAX + t] = tile[j2][tl];
    }
}

// ---------------------------------------------------------------------------
// One warp-synchronous chain step:
//   st.shared fv[j]; ld.shared.v2.b64 x4 (in-order LSU => RAW safe, no BAR);
//   fv' = max_p( fv[p] + a[p] ) + feat     (bit-exact vs reference)
// ---------------------------------------------------------------------------
__device__ __forceinline__ float chain_step(
    unsigned sbase, unsigned saddr_j, float fv, float feat,
    unsigned long long k0, unsigned long long k1,
    unsigned long long k2, unsigned long long k3,
    unsigned long long k4, unsigned long long k5,
    unsigned long long k6, unsigned long long k7)
{
    asm volatile("st.shared.f32 [%0], %1;" :: "r"(saddr_j), "f"(fv) : "memory");
    unsigned long long w0, w1, w2, w3, w4, w5, w6, w7;
    asm volatile("ld.shared.v2.b64 {%0,%1}, [%2];"
                 : "=l"(w0), "=l"(w1) : "r"(sbase)      : "memory");
    asm volatile("ld.shared.v2.b64 {%0,%1}, [%2];"
                 : "=l"(w2), "=l"(w3) : "r"(sbase + 16) : "memory");
    asm volatile("ld.shared.v2.b64 {%0,%1}, [%2];"
                 : "=l"(w4), "=l"(w5) : "r"(sbase + 32) : "memory");
    asm volatile("ld.shared.v2.b64 {%0,%1}, [%2];"
                 : "=l"(w6), "=l"(w7) : "r"(sbase + 48) : "memory");
    unsigned long long c0, c1, c2, c3, c4, c5, c6, c7;
    ADDX2(c0, w0, k0);  ADDX2(c1, w1, k1);
    ADDX2(c2, w2, k2);  ADDX2(c3, w3, k3);
    ADDX2(c4, w4, k4);  ADDX2(c5, w5, k5);
    ADDX2(c6, w6, k6);  ADDX2(c7, w7, k7);
    float v0, v1, v2, v3, v4, v5, v6, v7;
    float v8, v9, v10, v11, v12, v13, v14, v15;
    UNPKX2(v0,  v1,  c0);  UNPKX2(v2,  v3,  c1);
    UNPKX2(v4,  v5,  c2);  UNPKX2(v6,  v7,  c3);
    UNPKX2(v8,  v9,  c4);  UNPKX2(v10, v11, c5);
    UNPKX2(v12, v13, c6);  UNPKX2(v14, v15, c7);
    // exact max tree (fp max is order-independent)
    v0 = fmaxf(v0, v8);   v1 = fmaxf(v1, v9);
    v2 = fmaxf(v2, v10);  v3 = fmaxf(v3, v11);
    v4 = fmaxf(v4, v12);  v5 = fmaxf(v5, v13);
    v6 = fmaxf(v6, v14);  v7 = fmaxf(v7, v15);
    v0 = fmaxf(v0, v4);   v1 = fmaxf(v1, v5);
    v2 = fmaxf(v2, v6);   v3 = fmaxf(v3, v7);
    v0 = fmaxf(v0, v2);   v1 = fmaxf(v1, v3);
    v0 = fmaxf(v0, v1);
    return v0 + feat;
}

__global__ void __launch_bounds__(16, 1)
k_chain(const float* __restrict__ trans, int T)
{
    __shared__ __align__(64) float sS[16];
    const int j = threadIdx.x;        // tag

    unsigned sbase   = (unsigned)__cvta_generic_to_shared(&sS[0]);
    unsigned saddr_j = sbase + (unsigned)(j * 4);

    // A row j packed into 8 f32x2 constants
    unsigned long long k0, k1, k2, k3, k4, k5, k6, k7;
    {
        float4 q0 = reinterpret_cast<const float4*>(trans)[j * 4 + 0];
        float4 q1 = reinterpret_cast<const float4*>(trans)[j * 4 + 1];
        float4 q2 = reinterpret_cast<const float4*>(trans)[j * 4 + 2];
        float4 q3 = reinterpret_cast<const float4*>(trans)[j * 4 + 3];
        PKX2(k0, q0.x, q0.y);  PKX2(k1, q0.z, q0.w);
        PKX2(k2, q1.x, q1.y);  PKX2(k3, q1.z, q1.w);
        PKX2(k4, q2.x, q2.y);  PKX2(k5, q2.z, q2.w);
        PKX2(k6, q3.x, q3.y);  PKX2(k7, q3.z, q3.w);
    }

    const float* fj = g_ftr + (size_t)j * T_MAX;   // my feat row (transposed)
    float*       oj = g_fvt + (size_t)j * T_MAX;   // my fv row (transposed)

    float fv = 0.0f;

    // Main loop: groups of 16 steps; group g prefetches group g+1.
    int G = (T >= 32) ? ((T - 16) / 16) : 0;

    float4 cur[4], nxt[4];
    if (G > 0) {
#pragma unroll
        for (int q = 0; q < 4; q++) cur[q] = *(const float4*)(fj + q * 4);
    }

    for (int g = 0; g < G; g++) {
        const float* pf = fj + (size_t)(g + 1) * 16;
#pragma unroll
        for (int q = 0; q < 4; q++) nxt[q] = *(const float4*)(pf + q * 4);
        float* po = oj + (size_t)g * 16;
#pragma unroll
        for (int q = 0; q < 4; q++) {
            float4 f4 = cur[q];
            float4 acc;
            acc.x = fv = chain_step(sbase, saddr_j, fv, f4.x, k0,k1,k2,k3,k4,k5,k6,k7);
            acc.y = fv = chain_step(sbase, saddr_j, fv, f4.y, k0,k1,k2,k3,k4,k5,k6,k7);
            acc.z = fv = chain_step(sbase, saddr_j, fv, f4.z, k0,k1,k2,k3,k4,k5,k6,k7);
            acc.w = fv = chain_step(sbase, saddr_j, fv, f4.w, k0,k1,k2,k3,k4,k5,k6,k7);
            *(float4*)(po + q * 4) = acc;
        }
#pragma unroll
        for (int q = 0; q < 4; q++) cur[q] = nxt[q];
    }

    // Epilogue: remaining steps, scalar.
    for (int t = G * 16; t < T; t++) {
        fv = chain_step(sbase, saddr_j, fv, fj[t], k0,k1,k2,k3,k4,k5,k6,k7);
        oj[t] = fv;
    }
}

// ---------------------------------------------------------------------------
// K2: backpointers, grid-parallel. Thread handles (t, i).
// Strict '>' ascending scan keeps FIRST max (jnp.argmax). Scores recomputed
// with the identical single FADD -> bit-exact. Reads transposed fv.
// ---------------------------------------------------------------------------
__global__ void k_bp(const float* __restrict__ trans, int T)
{
    int idx = blockIdx.x * blockDim.x + threadIdx.x;
    if (idx >= T * KT) return;
    int t = idx >> 4;
    int i = idx & 15;

    float pv[16];
    if (t == 0) {
#pragma unroll
        for (int p = 0; p < 16; p++) pv[p] = 0.0f;
    } else {
#pragma unroll
        for (int p = 0; p < 16; p++)
            pv[p] = g_fvt[(size_t)p * T_MAX + (t - 1)];
    }

    float a[16];
#pragma unroll
    for (int q = 0; q < 4; q++) {
        float4 v = reinterpret_cast<const float4*>(trans)[i * 4 + q];
        a[4 * q + 0] = v.x; a[4 * q + 1] = v.y;
        a[4 * q + 2] = v.z; a[4 * q + 3] = v.w;
    }

    float best = pv[0] + a[0];
    int bi = 0;
#pragma unroll
    for (int p = 1; p < 16; p++) {
        float sc = pv[p] + a[p];
        if (sc > best) { best = sc; bi = p; }
    }
    g_bp[idx] = (unsigned char)bi;
}

// ---------------------------------------------------------------------------
// K3: per-chunk backward chase of all 16 exit-tag hypotheses.
// ---------------------------------------------------------------------------
__global__ void k_chunk(int T)
{
    __shared__ __align__(16) unsigned char sbp[CHUNK * KT];   // 32 KB
    int c = blockIdx.x;
    int s = c * CHUNK;
    int L = min(CHUNK, T - s);

    const int4* src = reinterpret_cast<const int4*>(g_bp + (size_t)s * KT);
    int4* dst = reinterpret_cast<int4*>(sbp);
    for (int i = threadIdx.x; i < L; i += blockDim.x) dst[i] = src[i];
    __syncthreads();

    if (threadIdx.x < 16) {
        int cur = threadIdx.x;
        for (int tt = L - 1; tt >= 0; tt--) {
            cur = sbp[tt * KT + cur];
            g_p16[(size_t)(s + tt) * KT + threadIdx.x] = (unsigned char)cur;
        }
        g_comp[c * KT + threadIdx.x] = (unsigned char)cur;
    }
}

// ---------------------------------------------------------------------------
// K3b: compose chunk maps right-to-left. Z starts at argmax(final fv).
// ---------------------------------------------------------------------------
__global__ void k_seed(int T, int C)
{
    __shared__ __align__(16) unsigned char sc[NCHUNK_MAX * KT];
    for (int i = threadIdx.x; i < C * KT; i += blockDim.x) sc[i] = g_comp[i];
    __syncthreads();

    if (threadIdx.x == 0) {
        float best = g_fvt[(size_t)0 * T_MAX + (T - 1)];
        int Z = 0;
#pragma unroll
        for (int i = 1; i < 16; i++) {
            float v = g_fvt[(size_t)i * T_MAX + (T - 1)];
            if (v > best) { best = v; Z = i; }
        }
        for (int c = C - 1; c >= 0; c--) {
            g_seed[c] = (unsigned char)Z;
            Z = sc[c * KT + Z];
        }
    }
}

// ---------------------------------------------------------------------------
// K4: final select.  out[t] = (float) path16[t][ seed[chunk(t)] ]
// ---------------------------------------------------------------------------
__global__ void k_out(float* __restrict__ out, int T)
{
    int t = blockIdx.x * blockDim.x + threadIdx.x;
    if (t < T) {
        int h = g_seed[t / CHUNK];
        out[t] = (float)g_p16[(size_t)t * KT + h];
    }
}

// ---------------------------------------------------------------------------
extern "C" void kernel_launch(void* const* d_in, const int* in_sizes, int n_in,
                              void* d_out, int out_size)
{
    // Input autodetect: transitions = 256-element tensor; sentence = large.
    int fi = 0;
    if (n_in >= 2 && in_sizes[1] > in_sizes[0]) fi = 1;
    const float* feats = (const float*)d_in[fi];
    const float* trans = (const float*)d_in[1 - fi];

    int T = in_sizes[fi] / KT;
    if (T > T_MAX) T = T_MAX;
    if (out_size > 0 && out_size < T) T = out_size;
    if (T < 1) return;
    int C = (T + CHUNK - 1) / CHUNK;

    // ncu alignment: 2 harness launches + 2 dummies + k_tr = 5 skipped,
    // capture lands on k_chain.
    k_dummy<<<1, 32>>>();
    k_dummy<<<1, 32>>>();

    k_tr<<<(T + 63) / 64, 256>>>(feats, T);
    k_chain<<<1, 16>>>(trans, T);
    k_bp<<<(T * KT + 255) / 256, 256>>>(trans, T);
    k_chunk<<<C, 128>>>(T);
    k_seed<<<1, 128>>>(T, C);
    k_out<<<(T + 255) / 256, 256>>>((float*)d_out, T);
}